// round 15
// baseline (speedup 1.0000x reference)
#include <cuda_runtime.h>
#include <cuda_fp16.h>
#include <cstdint>

#define SEQ   2048
#define EMB   1024
#define NH    16
#define HSZ   64
#define BATCH 2
#define ROWS  (BATCH * SEQ)     // 4096
#define D3    (3 * EMB)         // 3072
#define NCK   (EMB / 32)        // 32 k-stages of BK=32 for projection GEMMs

// Scratch (device globals — no allocation allowed)
__device__ __half g_qkv[ROWS * D3];    // qkv fp16 [b*s][3*EMB] (Q pre-scaled)
__device__ __half g_wt1[D3 * EMB];     // W_qkv^T fp16 [3072,1024] (K-major)
__device__ __half g_wt2[EMB * EMB];    // W_out^T fp16
__device__ __half g_x[ROWS * EMB];     // x fp16
__device__ __half g_o[ROWS * EMB];     // attn-out fp16

#define SCALE_L2E 0.180336880f         // 0.125 * log2(e)

// ============================================================================
// asm helpers (plain sm_80+ PTX — legal on target sm_103)
// ============================================================================
__device__ __forceinline__ uint32_t smem_to_u32(const void* p) {
    uint32_t a;
    asm("{ .reg .u64 t; cvta.to.shared.u64 t, %1; cvt.u32.u64 %0, t; }"
        : "=r"(a) : "l"(p));
    return a;
}

#define CP_ASYNC16(dst, src) \
    asm volatile("cp.async.cg.shared.global [%0], [%1], 16;" \
                 :: "r"(dst), "l"(__cvta_generic_to_global(src)) : "memory")
#define CP_COMMIT() asm volatile("cp.async.commit_group;" ::: "memory")
#define CP_WAIT1()  asm volatile("cp.async.wait_group 1;" ::: "memory")

#define LDSM_X4(r0, r1, r2, r3, addr) \
    asm volatile("ldmatrix.sync.aligned.m8n8.x4.shared.b16 {%0,%1,%2,%3}, [%4];" \
                 : "=r"(r0), "=r"(r1), "=r"(r2), "=r"(r3) : "r"(addr))
#define LDSM_X4T(r0, r1, r2, r3, addr) \
    asm volatile("ldmatrix.sync.aligned.m8n8.x4.trans.shared.b16 {%0,%1,%2,%3}, [%4];" \
                 : "=r"(r0), "=r"(r1), "=r"(r2), "=r"(r3) : "r"(addr))

#define MMA_F16(d, a, b0v, b1v) \
    asm volatile("mma.sync.aligned.m16n8k16.row.col.f32.f16.f16.f32 " \
                 "{%0,%1,%2,%3}, {%4,%5,%6,%7}, {%8,%9}, {%0,%1,%2,%3};" \
                 : "+f"((d)[0]), "+f"((d)[1]), "+f"((d)[2]), "+f"((d)[3]) \
                 : "r"((a)[0]), "r"((a)[1]), "r"((a)[2]), "r"((a)[3]), \
                   "r"(b0v), "r"(b1v))

// pack two f32 -> f16x2 (first arg in low half)
__device__ __forceinline__ uint32_t pack_f16x2(float lo, float hi) {
    uint32_t r;
    asm("cvt.rn.f16x2.f32 %0, %1, %2;" : "=r"(r) : "f"(hi), "f"(lo));
    return r;
}
#define H2EXP2(d, s) asm("ex2.approx.f16x2 %0, %1;" : "=r"(d) : "r"(s))
#define EX2F(d, s)   asm("ex2.approx.f32 %0, %1;"   : "=f"(d) : "f"(s))

// ============================================================================
// Unified prep (one launch): W_qkv^T, W_out^T (fp16), x (fp16).
// ============================================================================
__global__ void prep_all(const float* __restrict__ x,
                         const float* __restrict__ W_qkv,
                         const float* __restrict__ W_out)
{
    const int bid = blockIdx.x;
    const int tid = threadIdx.x;
    if (bid < 4096) {
        __shared__ float t[32][33];
        const float* W; __half* Wt; int K, N, n0, k0;
        if (bid < 3072) {
            W = W_qkv; Wt = g_wt1; K = EMB; N = D3;
            n0 = (bid % 96) * 32; k0 = (bid / 96) * 32;
        } else {
            const int b2 = bid - 3072;
            W = W_out; Wt = g_wt2; K = EMB; N = EMB;
            n0 = (b2 % 32) * 32; k0 = (b2 / 32) * 32;
        }
        const int tx = tid & 31, ty = tid >> 5;   // 32 x 8
#pragma unroll
        for (int j = 0; j < 32; j += 8)
            t[ty + j][tx] = W[(long)(k0 + ty + j) * N + n0 + tx];
        __syncthreads();
#pragma unroll
        for (int j = 0; j < 32; j += 8) {
            const int n = n0 + ty + j, k = k0 + tx;
            Wt[(long)n * K + k] = __float2half_rn(t[tx][ty + j]);
        }
    } else {
        const long i = (long)(bid - 4096) * 256 + tid;
        float4 v = ((const float4*)x)[i];
        uint2 u;
        u.x = pack_f16x2(v.x, v.y);
        u.y = pack_f16x2(v.z, v.w);
        ((uint2*)g_x)[i] = u;
    }
}

// ============================================================================
// HMMA GEMM + bias. LDSM bursts hoisted ahead of MMA bursts per kk.
// MODE 0 additionally pre-scales the Q region (cols < EMB) by SCALE_L2E.
// ============================================================================
#define STG 20480
#define GEMM_SMEM (4 * STG)

template <int MODE>
__global__ __launch_bounds__(256, 2)
void gemm_tc(const float* __restrict__ bias, float* __restrict__ Cout)
{
    const __half* A  = (MODE == 0) ? g_x : g_o;
    const __half* Bw = (MODE == 0) ? g_wt1 : g_wt2;
    const int N = (MODE == 0) ? D3 : EMB;
    const int K = EMB;

    extern __shared__ char smem[];
    const uint32_t sb = smem_to_u32(smem);
    const int tid = threadIdx.x;
    const int wid = tid >> 5, lane = tid & 31;
    const int wm = wid & 3, wn = wid >> 2;
    const int m0 = blockIdx.y * 128, n0 = blockIdx.x * 128;

    const __half* csrc[4];
    uint32_t cdst[4];
#pragma unroll
    for (int i = 0; i < 4; i++) {
        int g = i * 256 + tid;
        int sub = g >> 9, c = g & 511, row = c >> 2, ch = c & 3;
        const __half* bp = (sub == 0) ? A + (long)m0 * K : Bw + (long)n0 * K;
        csrc[i] = bp + (long)row * K + ch * 8;
        cdst[i] = sb + sub * 10240 + row * 80 + ch * 16;
    }

    auto issue_stage = [&](int s) {
        const uint32_t bo = (uint32_t)(s & 3) * STG;
        const bool real = (s < NCK);
#pragma unroll
        for (int i = 0; i < 4; i++) {
            const __half* src = real ? csrc[i] : csrc[i] - 32;
            CP_ASYNC16(cdst[i] + bo, src);
            if (real) csrc[i] += 32;
        }
    };

    issue_stage(0); issue_stage(1); CP_COMMIT();
    issue_stage(2); issue_stage(3); CP_COMMIT();

    const uint32_t a_base = sb + (wm * 32 + (lane & 15)) * 80 + (lane >> 4) * 16;
    const uint32_t b_base = sb + 10240 +
        (wn * 64 + (lane & 7) + ((lane >> 4) & 1) * 8) * 80 + ((lane >> 3) & 1) * 16;

    float acc[2][8][4];
#pragma unroll
    for (int mf = 0; mf < 2; mf++)
#pragma unroll
        for (int nf = 0; nf < 8; nf++)
#pragma unroll
            for (int q = 0; q < 4; q++) acc[mf][nf][q] = 0.f;

    auto compute_stage = [&](int ck) {
        const uint32_t bofs = (uint32_t)(ck & 3) * STG;
#pragma unroll
        for (int kk = 0; kk < 2; kk++) {
            const uint32_t ko = bofs + kk * 32;
            // ---- hoisted LDSM burst: all A + all B fragments for this kk ----
            uint32_t a4[2][4], b44[4][4];
            LDSM_X4(a4[0][0], a4[0][1], a4[0][2], a4[0][3], a_base + ko);
            LDSM_X4(a4[1][0], a4[1][1], a4[1][2], a4[1][3], a_base + 1280 + ko);
#pragma unroll
            for (int nf = 0; nf < 4; nf++)
                LDSM_X4(b44[nf][0], b44[nf][1], b44[nf][2], b44[nf][3],
                        b_base + nf * 1280 + ko);
            // ---- MMA burst: 16 MMAs, no smem dependency inside ----
#pragma unroll
            for (int nf = 0; nf < 4; nf++) {
                MMA_F16(acc[0][nf * 2 + 0], a4[0], b44[nf][0], b44[nf][1]);
                MMA_F16(acc[1][nf * 2 + 0], a4[1], b44[nf][0], b44[nf][1]);
                MMA_F16(acc[0][nf * 2 + 1], a4[0], b44[nf][2], b44[nf][3]);
                MMA_F16(acc[1][nf * 2 + 1], a4[1], b44[nf][2], b44[nf][3]);
            }
        }
    };

    for (int j = 0; j < NCK / 2; j++) {
        CP_WAIT1();
        __syncthreads();
        compute_stage(2 * j);
        compute_stage(2 * j + 1);
        __syncthreads();
        issue_stage(2 * j + 4);
        issue_stage(2 * j + 5);
        CP_COMMIT();
    }

    const int gid = lane >> 2, tig = lane & 3;
#pragma unroll
    for (int mf = 0; mf < 2; mf++) {
#pragma unroll
        for (int nf = 0; nf < 8; nf++) {
            const int col = n0 + wn * 64 + nf * 8 + tig * 2;
            const float bx0 = bias[col], bx1 = bias[col + 1];
            const int r0 = m0 + wm * 32 + mf * 16 + gid;
            float v00 = acc[mf][nf][0] + bx0, v01 = acc[mf][nf][1] + bx1;
            float v10 = acc[mf][nf][2] + bx0, v11 = acc[mf][nf][3] + bx1;
            if (MODE == 1) {
                float2 a0 = {v00, v01}, a1 = {v10, v11};
                *(float2*)&Cout[(long)r0 * N + col] = a0;
                *(float2*)&Cout[(long)(r0 + 8) * N + col] = a1;
            } else {
                if (n0 < EMB) {   // Q region: fold softmax scale into Q
                    v00 *= SCALE_L2E; v01 *= SCALE_L2E;
                    v10 *= SCALE_L2E; v11 *= SCALE_L2E;
                }
                *(uint32_t*)&g_qkv[(long)r0 * N + col] = pack_f16x2(v00, v01);
                *(uint32_t*)&g_qkv[(long)(r0 + 8) * N + col] = pack_f16x2(v10, v11);
            }
        }
    }
}

// ============================================================================
// HMMA flash attention v2, causal. 4 warps x 32 q-rows, Q in registers,
// ones-MMA row sums, ex2.approx.f16x2 exp. LDSM bursts hoisted per ks.
// ============================================================================
#define APITCH 144
#define SQ_BYTES  (128 * APITCH)          // 18432 (Q staging)
#define SKV_BYTES (64 * APITCH)           // 9216  (one K or V buffer)
#define ATTN_SMEM (SQ_BYTES + 8 * SKV_BYTES)   // 92160

__global__ __launch_bounds__(128, 2)
void attn_tc()
{
    extern __shared__ char smem[];
    const uint32_t sb = smem_to_u32(smem);
    const uint32_t sQ = sb;
    const uint32_t sK0 = sb + SQ_BYTES;              // K ring: + (s&3)*9216
    const uint32_t sV0 = sK0 + 4 * SKV_BYTES;        // V ring: + (s&3)*9216

    const int qt = gridDim.x - 1 - blockIdx.x;   // long blocks first
    const int h  = blockIdx.y;
    const int b  = blockIdx.z;
    const int tid = threadIdx.x;
    const int wid = tid >> 5, lane = tid & 31;
    const int gid = lane >> 2, tig = lane & 3;
    const int q0 = qt * 128;
    const long rowbase = (long)b * SEQ;
    const int nk = 2 * qt + 2;                   // even
    const uint32_t ONES = 0x3C003C00u;           // half2(1,1)

    auto issue_kv = [&](int s) {
        const int kr = (s < nk) ? s * 64 : 0;
        const uint32_t kb = sK0 + (uint32_t)(s & 3) * SKV_BYTES;
        const uint32_t vb = sV0 + (uint32_t)(s & 3) * SKV_BYTES;
#pragma unroll
        for (int it = 0; it < 4; it++) {
            int g = it * 128 + tid;
            int row = g >> 3, ch = g & 7;
            const __half* base = g_qkv + (rowbase + kr + row) * D3 + h * HSZ + ch * 8;
            CP_ASYNC16(kb + row * APITCH + ch * 16, base + EMB);
            CP_ASYNC16(vb + row * APITCH + ch * 16, base + 2 * EMB);
        }
    };

    // prologue: group0 = Q + K/V(0,1); group1 = K/V(2,3)
#pragma unroll
    for (int it = 0; it < 8; it++) {
        int g = it * 128 + tid;
        int row = g >> 3, ch = g & 7;
        const __half* src = g_qkv + (rowbase + q0 + row) * D3 + h * HSZ + ch * 8;
        CP_ASYNC16(sQ + row * APITCH + ch * 16, src);
    }
    issue_kv(0); issue_kv(1); CP_COMMIT();
    issue_kv(2); issue_kv(3); CP_COMMIT();

    const uint32_t bk_off = ((lane & 7) + ((lane >> 4) & 1) * 8) * APITCH
                              + ((lane >> 3) & 1) * 16;
    const uint32_t v_off = ((lane & 7) + ((lane >> 3) & 1) * 8) * APITCH
                              + (lane >> 4) * 16;

    uint32_t qreg[2][4][4];                      // [mf][ks][reg], loaded once
    float oacc[2][8][4];
    float lacc[2][4];
    float mrow[2][2];
#pragma unroll
    for (int mf = 0; mf < 2; mf++) {
        mrow[mf][0] = -1e30f; mrow[mf][1] = -1e30f;
#pragma unroll
        for (int q = 0; q < 4; q++) lacc[mf][q] = 0.f;
#pragma unroll
        for (int df = 0; df < 8; df++)
#pragma unroll
            for (int q = 0; q < 4; q++) oacc[mf][df][q] = 0.f;
    }

    const int qrA0 = q0 + wid * 32 + gid;        // mf0 rows: qrA0, qrA0+8

    auto do_stage = [&](int kt) {
        const int k0 = kt * 64;
        const uint32_t bufo = (uint32_t)(kt & 3) * SKV_BYTES;

        // ---- QK^T (hoisted K-LDSM bursts per ks) ----
        const uint32_t bk_base = sK0 + bufo + bk_off;
        float sacc[2][8][4];
#pragma unroll
        for (int mf = 0; mf < 2; mf++)
#pragma unroll
            for (int nf = 0; nf < 8; nf++)
#pragma unroll
                for (int q = 0; q < 4; q++) sacc[mf][nf][q] = 0.f;

#pragma unroll
        for (int ks = 0; ks < 4; ks++) {
            uint32_t k44[4][4];
#pragma unroll
            for (int nb = 0; nb < 4; nb++)
                LDSM_X4(k44[nb][0], k44[nb][1], k44[nb][2], k44[nb][3],
                        bk_base + nb * (16 * APITCH) + ks * 32);
#pragma unroll
            for (int nb = 0; nb < 4; nb++) {
                MMA_F16(sacc[0][nb * 2 + 0], qreg[0][ks], k44[nb][0], k44[nb][1]);
                MMA_F16(sacc[1][nb * 2 + 0], qreg[1][ks], k44[nb][0], k44[nb][1]);
                MMA_F16(sacc[0][nb * 2 + 1], qreg[0][ks], k44[nb][2], k44[nb][3]);
                MMA_F16(sacc[1][nb * 2 + 1], qreg[1][ks], k44[nb][2], k44[nb][3]);
            }
        }

        // ---- causal mask (only on diagonal stages) ----
        if (kt >= 2 * qt) {
#pragma unroll
            for (int mf = 0; mf < 2; mf++) {
                const int ra = qrA0 + mf * 16, rb = ra + 8;
#pragma unroll
                for (int nf = 0; nf < 8; nf++) {
                    const int c = k0 + nf * 8 + 2 * tig;
                    if (c     > ra) sacc[mf][nf][0] = -1e30f;
                    if (c + 1 > ra) sacc[mf][nf][1] = -1e30f;
                    if (c     > rb) sacc[mf][nf][2] = -1e30f;
                    if (c + 1 > rb) sacc[mf][nf][3] = -1e30f;
                }
            }
        }

        // ---- row max + online rescale + exp (fp16x2) + P frags ----
        uint32_t pa[2][4][4];
#pragma unroll
        for (int mf = 0; mf < 2; mf++) {
            float tm0 = -1e30f, tm1 = -1e30f;
#pragma unroll
            for (int nf = 0; nf < 8; nf++) {
                tm0 = fmaxf(tm0, fmaxf(sacc[mf][nf][0], sacc[mf][nf][1]));
                tm1 = fmaxf(tm1, fmaxf(sacc[mf][nf][2], sacc[mf][nf][3]));
            }
            tm0 = fmaxf(tm0, __shfl_xor_sync(0xffffffffu, tm0, 1));
            tm0 = fmaxf(tm0, __shfl_xor_sync(0xffffffffu, tm0, 2));
            tm1 = fmaxf(tm1, __shfl_xor_sync(0xffffffffu, tm1, 1));
            tm1 = fmaxf(tm1, __shfl_xor_sync(0xffffffffu, tm1, 2));

            const float mn0 = fmaxf(mrow[mf][0], tm0);
            const float mn1 = fmaxf(mrow[mf][1], tm1);
            float esc0, esc1;
            EX2F(esc0, mrow[mf][0] - mn0);
            EX2F(esc1, mrow[mf][1] - mn1);
            mrow[mf][0] = mn0; mrow[mf][1] = mn1;
#pragma unroll
            for (int df = 0; df < 8; df++) {
                oacc[mf][df][0] *= esc0; oacc[mf][df][1] *= esc0;
                oacc[mf][df][2] *= esc1; oacc[mf][df][3] *= esc1;
            }
            lacc[mf][0] *= esc0; lacc[mf][1] *= esc0;
            lacc[mf][2] *= esc1; lacc[mf][3] *= esc1;

#pragma unroll
            for (int ks = 0; ks < 4; ks++) {
                const int f0 = 2 * ks, f1 = 2 * ks + 1;
                uint32_t d0 = pack_f16x2(sacc[mf][f0][0] - mn0, sacc[mf][f0][1] - mn0);
                uint32_t d1 = pack_f16x2(sacc[mf][f0][2] - mn1, sacc[mf][f0][3] - mn1);
                uint32_t d2 = pack_f16x2(sacc[mf][f1][0] - mn0, sacc[mf][f1][1] - mn0);
                uint32_t d3 = pack_f16x2(sacc[mf][f1][2] - mn1, sacc[mf][f1][3] - mn1);
                H2EXP2(pa[mf][ks][0], d0);
                H2EXP2(pa[mf][ks][1], d1);
                H2EXP2(pa[mf][ks][2], d2);
                H2EXP2(pa[mf][ks][3], d3);
            }
            // row sums via ones-MMA (accumulates into lacc)
#pragma unroll
            for (int ks = 0; ks < 4; ks++)
                MMA_F16(lacc[mf], pa[mf][ks], ONES, ONES);
        }

        // ---- PV (hoisted V-LDSM bursts per ks) ----
        const uint32_t v_base = sV0 + bufo + v_off;
#pragma unroll
        for (int ks = 0; ks < 4; ks++) {
            uint32_t v44[4][4];
#pragma unroll
            for (int nb = 0; nb < 4; nb++)
                LDSM_X4T(v44[nb][0], v44[nb][1], v44[nb][2], v44[nb][3],
                         v_base + ks * (16 * APITCH) + nb * 32);
#pragma unroll
            for (int nb = 0; nb < 4; nb++) {
                MMA_F16(oacc[0][nb * 2 + 0], pa[0][ks], v44[nb][0], v44[nb][1]);
                MMA_F16(oacc[1][nb * 2 + 0], pa[1][ks], v44[nb][0], v44[nb][1]);
                MMA_F16(oacc[0][nb * 2 + 1], pa[0][ks], v44[nb][2], v44[nb][3]);
                MMA_F16(oacc[1][nb * 2 + 1], pa[1][ks], v44[nb][2], v44[nb][3]);
            }
        }
    };

    for (int j = 0; j < nk / 2; j++) {
        CP_WAIT1();            // group j (K/V 2j,2j+1; +Q on j=0) landed
        __syncthreads();
        if (j == 0) {
#pragma unroll
            for (int mf = 0; mf < 2; mf++) {
                const uint32_t qb = sQ + (wid * 32 + mf * 16 + (lane & 15)) * APITCH
                                    + (lane >> 4) * 16;
#pragma unroll
                for (int ks = 0; ks < 4; ks++)
                    LDSM_X4(qreg[mf][ks][0], qreg[mf][ks][1],
                            qreg[mf][ks][2], qreg[mf][ks][3], qb + ks * 32);
            }
        }
        do_stage(2 * j);
        do_stage(2 * j + 1);
        __syncthreads();
        issue_kv(2 * j + 4);
        issue_kv(2 * j + 5);
        CP_COMMIT();
    }

    // ---- finalize: O = oacc / l (l from ones-MMA accumulator), fp16 ----
#pragma unroll
    for (int mf = 0; mf < 2; mf++) {
        const float inv0 = 1.f / lacc[mf][0];
        const float inv1 = 1.f / lacc[mf][2];
        const int ra = qrA0 + mf * 16, rb = ra + 8;
#pragma unroll
        for (int df = 0; df < 8; df++) {
            const int col = h * HSZ + df * 8 + 2 * tig;
            *(uint32_t*)&g_o[(rowbase + ra) * EMB + col] =
                pack_f16x2(oacc[mf][df][0] * inv0, oacc[mf][df][1] * inv0);
            *(uint32_t*)&g_o[(rowbase + rb) * EMB + col] =
                pack_f16x2(oacc[mf][df][2] * inv1, oacc[mf][df][3] * inv1);
        }
    }
}

// ---------------------------------------------------------------------------
extern "C" void kernel_launch(void* const* d_in, const int* in_sizes, int n_in,
                              void* d_out, int out_size)
{
    const float* x     = (const float*)d_in[0];
    const float* W_qkv = (const float*)d_in[1];
    const float* b_qkv = (const float*)d_in[2];
    const float* W_out = (const float*)d_in[3];
    const float* b_out = (const float*)d_in[4];
    float* out = (float*)d_out;

    // 0) unified prep: W transposes (fp16) + x convert — one launch
    prep_all<<<8192, 256>>>(x, W_qkv, W_out);

    // 1) QKV projection (HMMA fp16; Q region pre-scaled by 0.125*log2e)
    cudaFuncSetAttribute(gemm_tc<0>, cudaFuncAttributeMaxDynamicSharedMemorySize, GEMM_SMEM);
    gemm_tc<0><<<dim3(D3 / 128, ROWS / 128), 256, GEMM_SMEM>>>(b_qkv, nullptr);

    // 2) causal flash attention v2 (hoisted LDSM bursts)
    cudaFuncSetAttribute(attn_tc, cudaFuncAttributeMaxDynamicSharedMemorySize, ATTN_SMEM);
    attn_tc<<<dim3(SEQ / 128, NH, BATCH), 128, ATTN_SMEM>>>();

    // 3) output projection (HMMA fp16), fp32 out + bias
    cudaFuncSetAttribute(gemm_tc<1>, cudaFuncAttributeMaxDynamicSharedMemorySize, GEMM_SMEM);
    gemm_tc<1><<<dim3(EMB / 128, ROWS / 128), 256, GEMM_SMEM>>>(b_out, out);
}

// round 16
// speedup vs baseline: 1.0125x; 1.0125x over previous
#include <cuda_runtime.h>
#include <cuda_fp16.h>
#include <cstdint>

#define SEQ   2048
#define EMB   1024
#define NH    16
#define HSZ   64
#define BATCH 2
#define ROWS  (BATCH * SEQ)     // 4096
#define D3    (3 * EMB)         // 3072
#define NCK   (EMB / 32)        // 32 k-stages of BK=32 for projection GEMMs

// Scratch (device globals — no allocation allowed)
__device__ __half g_qkv[ROWS * D3];    // qkv fp16 [b*s][3*EMB] (Q pre-scaled)
__device__ __half g_wt1[D3 * EMB];     // W_qkv^T fp16 [3072,1024] (K-major)
__device__ __half g_wt2[EMB * EMB];    // W_out^T fp16
__device__ __half g_x[ROWS * EMB];     // x fp16
__device__ __half g_o[ROWS * EMB];     // attn-out fp16

#define SCALE_L2E 0.180336880f         // 0.125 * log2(e)

// ============================================================================
// asm helpers (plain sm_80+ PTX — legal on target sm_103)
// ============================================================================
__device__ __forceinline__ uint32_t smem_to_u32(const void* p) {
    uint32_t a;
    asm("{ .reg .u64 t; cvta.to.shared.u64 t, %1; cvt.u32.u64 %0, t; }"
        : "=r"(a) : "l"(p));
    return a;
}

#define CP_ASYNC16(dst, src) \
    asm volatile("cp.async.cg.shared.global [%0], [%1], 16;" \
                 :: "r"(dst), "l"(__cvta_generic_to_global(src)) : "memory")
#define CP_COMMIT() asm volatile("cp.async.commit_group;" ::: "memory")
#define CP_WAIT1()  asm volatile("cp.async.wait_group 1;" ::: "memory")

#define LDSM_X4(r0, r1, r2, r3, addr) \
    asm volatile("ldmatrix.sync.aligned.m8n8.x4.shared.b16 {%0,%1,%2,%3}, [%4];" \
                 : "=r"(r0), "=r"(r1), "=r"(r2), "=r"(r3) : "r"(addr))
#define LDSM_X4T(r0, r1, r2, r3, addr) \
    asm volatile("ldmatrix.sync.aligned.m8n8.x4.trans.shared.b16 {%0,%1,%2,%3}, [%4];" \
                 : "=r"(r0), "=r"(r1), "=r"(r2), "=r"(r3) : "r"(addr))

#define MMA_F16(d, a, b0v, b1v) \
    asm volatile("mma.sync.aligned.m16n8k16.row.col.f32.f16.f16.f32 " \
                 "{%0,%1,%2,%3}, {%4,%5,%6,%7}, {%8,%9}, {%0,%1,%2,%3};" \
                 : "+f"((d)[0]), "+f"((d)[1]), "+f"((d)[2]), "+f"((d)[3]) \
                 : "r"((a)[0]), "r"((a)[1]), "r"((a)[2]), "r"((a)[3]), \
                   "r"(b0v), "r"(b1v))

// pack two f32 -> f16x2 (first arg in low half)
__device__ __forceinline__ uint32_t pack_f16x2(float lo, float hi) {
    uint32_t r;
    asm("cvt.rn.f16x2.f32 %0, %1, %2;" : "=r"(r) : "f"(hi), "f"(lo));
    return r;
}
#define H2EXP2(d, s) asm("ex2.approx.f16x2 %0, %1;" : "=r"(d) : "r"(s))
#define EX2F(d, s)   asm("ex2.approx.f32 %0, %1;"   : "=f"(d) : "f"(s))

// ============================================================================
// Unified prep (one launch): W_qkv^T, W_out^T (fp16), x (fp16).
// ============================================================================
__global__ void prep_all(const float* __restrict__ x,
                         const float* __restrict__ W_qkv,
                         const float* __restrict__ W_out)
{
    const int bid = blockIdx.x;
    const int tid = threadIdx.x;
    if (bid < 4096) {
        __shared__ float t[32][33];
        const float* W; __half* Wt; int K, N, n0, k0;
        if (bid < 3072) {
            W = W_qkv; Wt = g_wt1; K = EMB; N = D3;
            n0 = (bid % 96) * 32; k0 = (bid / 96) * 32;
        } else {
            const int b2 = bid - 3072;
            W = W_out; Wt = g_wt2; K = EMB; N = EMB;
            n0 = (b2 % 32) * 32; k0 = (b2 / 32) * 32;
        }
        const int tx = tid & 31, ty = tid >> 5;   // 32 x 8
#pragma unroll
        for (int j = 0; j < 32; j += 8)
            t[ty + j][tx] = W[(long)(k0 + ty + j) * N + n0 + tx];
        __syncthreads();
#pragma unroll
        for (int j = 0; j < 32; j += 8) {
            const int n = n0 + ty + j, k = k0 + tx;
            Wt[(long)n * K + k] = __float2half_rn(t[tx][ty + j]);
        }
    } else {
        const long i = (long)(bid - 4096) * 256 + tid;
        float4 v = ((const float4*)x)[i];
        uint2 u;
        u.x = pack_f16x2(v.x, v.y);
        u.y = pack_f16x2(v.z, v.w);
        ((uint2*)g_x)[i] = u;
    }
}

// ============================================================================
// HMMA GEMM + bias (at mma.sync ceiling — unchanged).
// MODE 0 additionally pre-scales the Q region (cols < EMB) by SCALE_L2E.
// ============================================================================
#define STG 20480
#define GEMM_SMEM (4 * STG)

template <int MODE>
__global__ __launch_bounds__(256, 2)
void gemm_tc(const float* __restrict__ bias, float* __restrict__ Cout)
{
    const __half* A  = (MODE == 0) ? g_x : g_o;
    const __half* Bw = (MODE == 0) ? g_wt1 : g_wt2;
    const int N = (MODE == 0) ? D3 : EMB;
    const int K = EMB;

    extern __shared__ char smem[];
    const uint32_t sb = smem_to_u32(smem);
    const int tid = threadIdx.x;
    const int wid = tid >> 5, lane = tid & 31;
    const int wm = wid & 3, wn = wid >> 2;
    const int m0 = blockIdx.y * 128, n0 = blockIdx.x * 128;

    const __half* csrc[4];
    uint32_t cdst[4];
#pragma unroll
    for (int i = 0; i < 4; i++) {
        int g = i * 256 + tid;
        int sub = g >> 9, c = g & 511, row = c >> 2, ch = c & 3;
        const __half* bp = (sub == 0) ? A + (long)m0 * K : Bw + (long)n0 * K;
        csrc[i] = bp + (long)row * K + ch * 8;
        cdst[i] = sb + sub * 10240 + row * 80 + ch * 16;
    }

    auto issue_stage = [&](int s) {
        const uint32_t bo = (uint32_t)(s & 3) * STG;
        const bool real = (s < NCK);
#pragma unroll
        for (int i = 0; i < 4; i++) {
            const __half* src = real ? csrc[i] : csrc[i] - 32;
            CP_ASYNC16(cdst[i] + bo, src);
            if (real) csrc[i] += 32;
        }
    };

    issue_stage(0); issue_stage(1); CP_COMMIT();
    issue_stage(2); issue_stage(3); CP_COMMIT();

    const uint32_t a_base = sb + (wm * 32 + (lane & 15)) * 80 + (lane >> 4) * 16;
    const uint32_t b_base = sb + 10240 +
        (wn * 64 + (lane & 7) + ((lane >> 4) & 1) * 8) * 80 + ((lane >> 3) & 1) * 16;

    float acc[2][8][4];
#pragma unroll
    for (int mf = 0; mf < 2; mf++)
#pragma unroll
        for (int nf = 0; nf < 8; nf++)
#pragma unroll
            for (int q = 0; q < 4; q++) acc[mf][nf][q] = 0.f;

    auto compute_stage = [&](int ck) {
        const uint32_t bofs = (uint32_t)(ck & 3) * STG;
#pragma unroll
        for (int kk = 0; kk < 2; kk++) {
            const uint32_t ko = bofs + kk * 32;
            uint32_t a4[2][4], b44[4][4];
            LDSM_X4(a4[0][0], a4[0][1], a4[0][2], a4[0][3], a_base + ko);
            LDSM_X4(a4[1][0], a4[1][1], a4[1][2], a4[1][3], a_base + 1280 + ko);
#pragma unroll
            for (int nf = 0; nf < 4; nf++)
                LDSM_X4(b44[nf][0], b44[nf][1], b44[nf][2], b44[nf][3],
                        b_base + nf * 1280 + ko);
#pragma unroll
            for (int nf = 0; nf < 4; nf++) {
                MMA_F16(acc[0][nf * 2 + 0], a4[0], b44[nf][0], b44[nf][1]);
                MMA_F16(acc[1][nf * 2 + 0], a4[1], b44[nf][0], b44[nf][1]);
                MMA_F16(acc[0][nf * 2 + 1], a4[0], b44[nf][2], b44[nf][3]);
                MMA_F16(acc[1][nf * 2 + 1], a4[1], b44[nf][2], b44[nf][3]);
            }
        }
    };

    for (int j = 0; j < NCK / 2; j++) {
        CP_WAIT1();
        __syncthreads();
        compute_stage(2 * j);
        compute_stage(2 * j + 1);
        __syncthreads();
        issue_stage(2 * j + 4);
        issue_stage(2 * j + 5);
        CP_COMMIT();
    }

    const int gid = lane >> 2, tig = lane & 3;
#pragma unroll
    for (int mf = 0; mf < 2; mf++) {
#pragma unroll
        for (int nf = 0; nf < 8; nf++) {
            const int col = n0 + wn * 64 + nf * 8 + tig * 2;
            const float bx0 = bias[col], bx1 = bias[col + 1];
            const int r0 = m0 + wm * 32 + mf * 16 + gid;
            float v00 = acc[mf][nf][0] + bx0, v01 = acc[mf][nf][1] + bx1;
            float v10 = acc[mf][nf][2] + bx0, v11 = acc[mf][nf][3] + bx1;
            if (MODE == 1) {
                float2 a0 = {v00, v01}, a1 = {v10, v11};
                *(float2*)&Cout[(long)r0 * N + col] = a0;
                *(float2*)&Cout[(long)(r0 + 8) * N + col] = a1;
            } else {
                if (n0 < EMB) {   // Q region: fold softmax scale into Q
                    v00 *= SCALE_L2E; v01 *= SCALE_L2E;
                    v10 *= SCALE_L2E; v11 *= SCALE_L2E;
                }
                *(uint32_t*)&g_qkv[(long)r0 * N + col] = pack_f16x2(v00, v01);
                *(uint32_t*)&g_qkv[(long)(r0 + 8) * N + col] = pack_f16x2(v10, v11);
            }
        }
    }
}

// ============================================================================
// HMMA flash attention v3, causal. 4 warps x 32 q-rows, Q in registers,
// ones-MMA row sums, ex2.approx.f16x2 exp.
// PV(s-1) deferred and issued between QK(s) and softmax(s) so the softmax
// scalar block overlaps in-flight PV MMAs. V ring = 5 slots (survives the
// one-stage deferral); K ring = 4 slots. Fully-masked warps skip QK on the
// final diagonal stage.
// ============================================================================
#define APITCH 144
#define SQ_BYTES  (128 * APITCH)          // 18432 (Q staging)
#define SKV_BYTES (64 * APITCH)           // 9216  (one K or V buffer)
#define ATTN_SMEM (SQ_BYTES + 4 * SKV_BYTES + 5 * SKV_BYTES)   // 101376

__global__ __launch_bounds__(128, 2)
void attn_tc()
{
    extern __shared__ char smem[];
    const uint32_t sb = smem_to_u32(smem);
    const uint32_t sQ = sb;
    const uint32_t sK0 = sb + SQ_BYTES;              // K ring: + (s&3)*9216
    const uint32_t sV0 = sK0 + 4 * SKV_BYTES;        // V ring: + (s%5)*9216

    const int qt = gridDim.x - 1 - blockIdx.x;   // long blocks first
    const int h  = blockIdx.y;
    const int b  = blockIdx.z;
    const int tid = threadIdx.x;
    const int wid = tid >> 5, lane = tid & 31;
    const int gid = lane >> 2, tig = lane & 3;
    const int q0 = qt * 128;
    const long rowbase = (long)b * SEQ;
    const int nk = 2 * qt + 2;                   // even
    const uint32_t ONES = 0x3C003C00u;           // half2(1,1)

    auto issue_k = [&](int s) {
        const int kr = (s < nk) ? s * 64 : 0;
        const uint32_t kb = sK0 + (uint32_t)(s & 3) * SKV_BYTES;
#pragma unroll
        for (int it = 0; it < 4; it++) {
            int g = it * 128 + tid;
            int row = g >> 3, ch = g & 7;
            CP_ASYNC16(kb + row * APITCH + ch * 16,
                       g_qkv + (rowbase + kr + row) * D3 + EMB + h * HSZ + ch * 8);
        }
    };
    auto issue_v = [&](int s) {
        const int kr = (s < nk) ? s * 64 : 0;
        const uint32_t vb = sV0 + (uint32_t)(s % 5) * SKV_BYTES;
#pragma unroll
        for (int it = 0; it < 4; it++) {
            int g = it * 128 + tid;
            int row = g >> 3, ch = g & 7;
            CP_ASYNC16(vb + row * APITCH + ch * 16,
                       g_qkv + (rowbase + kr + row) * D3 + 2 * EMB + h * HSZ + ch * 8);
        }
    };

    // prologue: group0 = Q + K/V(0,1); group1 = K/V(2,3)
#pragma unroll
    for (int it = 0; it < 8; it++) {
        int g = it * 128 + tid;
        int row = g >> 3, ch = g & 7;
        CP_ASYNC16(sQ + row * APITCH + ch * 16,
                   g_qkv + (rowbase + q0 + row) * D3 + h * HSZ + ch * 8);
    }
    issue_k(0); issue_k(1); issue_v(0); issue_v(1); CP_COMMIT();
    issue_k(2); issue_k(3); issue_v(2); issue_v(3); CP_COMMIT();

    const uint32_t bk_off = ((lane & 7) + ((lane >> 4) & 1) * 8) * APITCH
                              + ((lane >> 3) & 1) * 16;
    const uint32_t v_off = ((lane & 7) + ((lane >> 3) & 1) * 8) * APITCH
                              + (lane >> 4) * 16;

    uint32_t qreg[2][4][4];                      // [mf][ks][reg], loaded once
    float oacc[2][8][4];
    float lacc[2][4];
    float mrow[2][2];
    float sacc[2][8][4];
    uint32_t pa[2][4][4];                        // P frags (persist one stage)
#pragma unroll
    for (int mf = 0; mf < 2; mf++) {
        mrow[mf][0] = -1e30f; mrow[mf][1] = -1e30f;
#pragma unroll
        for (int q = 0; q < 4; q++) lacc[mf][q] = 0.f;
#pragma unroll
        for (int df = 0; df < 8; df++)
#pragma unroll
            for (int q = 0; q < 4; q++) oacc[mf][df][q] = 0.f;
    }

    const int qrA0 = q0 + wid * 32 + gid;        // mf0 rows: qrA0, qrA0+8

    // ---- QK^T for stage kt: sacc = Qreg x K[slot kt&3] ----
    auto do_qk = [&](int kt) {
        const uint32_t bk_base = sK0 + (uint32_t)(kt & 3) * SKV_BYTES + bk_off;
#pragma unroll
        for (int mf = 0; mf < 2; mf++)
#pragma unroll
            for (int nf = 0; nf < 8; nf++)
#pragma unroll
                for (int q = 0; q < 4; q++) sacc[mf][nf][q] = 0.f;
#pragma unroll
        for (int ks = 0; ks < 4; ks++) {
            uint32_t k44[4][4];
#pragma unroll
            for (int nb = 0; nb < 4; nb++)
                LDSM_X4(k44[nb][0], k44[nb][1], k44[nb][2], k44[nb][3],
                        bk_base + nb * (16 * APITCH) + ks * 32);
#pragma unroll
            for (int nb = 0; nb < 4; nb++) {
                MMA_F16(sacc[0][nb * 2 + 0], qreg[0][ks], k44[nb][0], k44[nb][1]);
                MMA_F16(sacc[1][nb * 2 + 0], qreg[1][ks], k44[nb][0], k44[nb][1]);
                MMA_F16(sacc[0][nb * 2 + 1], qreg[0][ks], k44[nb][2], k44[nb][3]);
                MMA_F16(sacc[1][nb * 2 + 1], qreg[1][ks], k44[nb][2], k44[nb][3]);
            }
        }
    };

    // ---- PV for stage kt: oacc += pa x V[slot kt%5] ----
    auto do_pv = [&](int kt) {
        const uint32_t v_base = sV0 + (uint32_t)(kt % 5) * SKV_BYTES + v_off;
#pragma unroll
        for (int ks = 0; ks < 4; ks++) {
            uint32_t v44[4][4];
#pragma unroll
            for (int nb = 0; nb < 4; nb++)
                LDSM_X4T(v44[nb][0], v44[nb][1], v44[nb][2], v44[nb][3],
                         v_base + ks * (16 * APITCH) + nb * 32);
#pragma unroll
            for (int nb = 0; nb < 4; nb++) {
                MMA_F16(oacc[0][nb * 2 + 0], pa[0][ks], v44[nb][0], v44[nb][1]);
                MMA_F16(oacc[1][nb * 2 + 0], pa[1][ks], v44[nb][0], v44[nb][1]);
                MMA_F16(oacc[0][nb * 2 + 1], pa[0][ks], v44[nb][2], v44[nb][3]);
                MMA_F16(oacc[1][nb * 2 + 1], pa[1][ks], v44[nb][2], v44[nb][3]);
            }
        }
    };

    // ---- softmax for stage kt: mask, max, rescale, pa = exp2, l-MMA ----
    auto do_sm = [&](int kt) {
        const int k0 = kt * 64;
        if (kt >= 2 * qt) {
#pragma unroll
            for (int mf = 0; mf < 2; mf++) {
                const int ra = qrA0 + mf * 16, rb = ra + 8;
#pragma unroll
                for (int nf = 0; nf < 8; nf++) {
                    const int c = k0 + nf * 8 + 2 * tig;
                    if (c     > ra) sacc[mf][nf][0] = -1e30f;
                    if (c + 1 > ra) sacc[mf][nf][1] = -1e30f;
                    if (c     > rb) sacc[mf][nf][2] = -1e30f;
                    if (c + 1 > rb) sacc[mf][nf][3] = -1e30f;
                }
            }
        }
#pragma unroll
        for (int mf = 0; mf < 2; mf++) {
            float tm0 = -1e30f, tm1 = -1e30f;
#pragma unroll
            for (int nf = 0; nf < 8; nf++) {
                tm0 = fmaxf(tm0, fmaxf(sacc[mf][nf][0], sacc[mf][nf][1]));
                tm1 = fmaxf(tm1, fmaxf(sacc[mf][nf][2], sacc[mf][nf][3]));
            }
            tm0 = fmaxf(tm0, __shfl_xor_sync(0xffffffffu, tm0, 1));
            tm0 = fmaxf(tm0, __shfl_xor_sync(0xffffffffu, tm0, 2));
            tm1 = fmaxf(tm1, __shfl_xor_sync(0xffffffffu, tm1, 1));
            tm1 = fmaxf(tm1, __shfl_xor_sync(0xffffffffu, tm1, 2));

            const float mn0 = fmaxf(mrow[mf][0], tm0);
            const float mn1 = fmaxf(mrow[mf][1], tm1);
            float esc0, esc1;
            EX2F(esc0, mrow[mf][0] - mn0);
            EX2F(esc1, mrow[mf][1] - mn1);
            mrow[mf][0] = mn0; mrow[mf][1] = mn1;
#pragma unroll
            for (int df = 0; df < 8; df++) {
                oacc[mf][df][0] *= esc0; oacc[mf][df][1] *= esc0;
                oacc[mf][df][2] *= esc1; oacc[mf][df][3] *= esc1;
            }
            lacc[mf][0] *= esc0; lacc[mf][1] *= esc0;
            lacc[mf][2] *= esc1; lacc[mf][3] *= esc1;

#pragma unroll
            for (int ks = 0; ks < 4; ks++) {
                const int f0 = 2 * ks, f1 = 2 * ks + 1;
                uint32_t d0 = pack_f16x2(sacc[mf][f0][0] - mn0, sacc[mf][f0][1] - mn0);
                uint32_t d1 = pack_f16x2(sacc[mf][f0][2] - mn1, sacc[mf][f0][3] - mn1);
                uint32_t d2 = pack_f16x2(sacc[mf][f1][0] - mn0, sacc[mf][f1][1] - mn0);
                uint32_t d3 = pack_f16x2(sacc[mf][f1][2] - mn1, sacc[mf][f1][3] - mn1);
                H2EXP2(pa[mf][ks][0], d0);
                H2EXP2(pa[mf][ks][1], d1);
                H2EXP2(pa[mf][ks][2], d2);
                H2EXP2(pa[mf][ks][3], d3);
            }
#pragma unroll
            for (int ks = 0; ks < 4; ks++)
                MMA_F16(lacc[mf], pa[mf][ks], ONES, ONES);
        }
    };

    for (int j = 0; j < nk / 2; j++) {
        CP_WAIT1();            // K/V stages 2j,2j+1 (+Q on j=0) landed
        __syncthreads();
        if (j == 0) {
#pragma unroll
            for (int mf = 0; mf < 2; mf++) {
                const uint32_t qb = sQ + (wid * 32 + mf * 16 + (lane & 15)) * APITCH
                                    + (lane >> 4) * 16;
#pragma unroll
                for (int ks = 0; ks < 4; ks++)
                    LDSM_X4(qreg[mf][ks][0], qreg[mf][ks][1],
                            qreg[mf][ks][2], qreg[mf][ks][3], qb + ks * 32);
            }
        }
        const int a = 2 * j, bs = 2 * j + 1;
        // fully-masked warps on the final diagonal stage skip their QK burst
        const bool deadb = (j == qt) && (wid < 2);

        do_qk(a);
        if (j > 0) do_pv(a - 1);     // deferred PV overlaps softmax(a) issue
        do_sm(a);

        if (!deadb) do_qk(bs);       // (mask in do_sm overwrites stale sacc)
        do_pv(a);                    // overlaps softmax(bs) issue
        do_sm(bs);

        __syncthreads();
        issue_k(2 * j + 4); issue_k(2 * j + 5);
        issue_v(2 * j + 4); issue_v(2 * j + 5);
        CP_COMMIT();
    }
    do_pv(nk - 1);                   // final deferred PV

    // ---- finalize: O = oacc / l (l from ones-MMA accumulator), fp16 ----
#pragma unroll
    for (int mf = 0; mf < 2; mf++) {
        const float inv0 = 1.f / lacc[mf][0];
        const float inv1 = 1.f / lacc[mf][2];
        const int ra = qrA0 + mf * 16, rb = ra + 8;
#pragma unroll
        for (int df = 0; df < 8; df++) {
            const int col = h * HSZ + df * 8 + 2 * tig;
            *(uint32_t*)&g_o[(rowbase + ra) * EMB + col] =
                pack_f16x2(oacc[mf][df][0] * inv0, oacc[mf][df][1] * inv0);
            *(uint32_t*)&g_o[(rowbase + rb) * EMB + col] =
                pack_f16x2(oacc[mf][df][2] * inv1, oacc[mf][df][3] * inv1);
        }
    }
}

// ---------------------------------------------------------------------------
extern "C" void kernel_launch(void* const* d_in, const int* in_sizes, int n_in,
                              void* d_out, int out_size)
{
    const float* x     = (const float*)d_in[0];
    const float* W_qkv = (const float*)d_in[1];
    const float* b_qkv = (const float*)d_in[2];
    const float* W_out = (const float*)d_in[3];
    const float* b_out = (const float*)d_in[4];
    float* out = (float*)d_out;

    // 0) unified prep: W transposes (fp16) + x convert — one launch
    prep_all<<<8192, 256>>>(x, W_qkv, W_out);

    // 1) QKV projection (HMMA fp16; Q region pre-scaled by 0.125*log2e)
    cudaFuncSetAttribute(gemm_tc<0>, cudaFuncAttributeMaxDynamicSharedMemorySize, GEMM_SMEM);
    gemm_tc<0><<<dim3(D3 / 128, ROWS / 128), 256, GEMM_SMEM>>>(b_qkv, nullptr);

    // 2) causal flash attention v3 (deferred-PV softmax overlap)
    cudaFuncSetAttribute(attn_tc, cudaFuncAttributeMaxDynamicSharedMemorySize, ATTN_SMEM);
    attn_tc<<<dim3(SEQ / 128, NH, BATCH), 128, ATTN_SMEM>>>();

    // 3) output projection (HMMA fp16), fp32 out + bias
    cudaFuncSetAttribute(gemm_tc<1>, cudaFuncAttributeMaxDynamicSharedMemorySize, GEMM_SMEM);
    gemm_tc<1><<<dim3(EMB / 128, ROWS / 128), 256, GEMM_SMEM>>>(b_out, out);
}

// round 17
// speedup vs baseline: 1.0222x; 1.0095x over previous
#include <cuda_runtime.h>
#include <cuda_fp16.h>
#include <cstdint>

#define SEQ   2048
#define EMB   1024
#define NH    16
#define HSZ   64
#define BATCH 2
#define ROWS  (BATCH * SEQ)     // 4096
#define D3    (3 * EMB)         // 3072
#define NCK   (EMB / 32)        // 32 k-stages of BK=32 for projection GEMMs

// Scratch (device globals — no allocation allowed)
__device__ __half g_qkv[ROWS * D3];    // qkv fp16 [b*s][3*EMB] (Q pre-scaled)
__device__ __half g_wt1[D3 * EMB];     // W_qkv^T fp16 [3072,1024] (K-major)
__device__ __half g_wt2[EMB * EMB];    // W_out^T fp16
__device__ __half g_x[ROWS * EMB];     // x fp16
__device__ __half g_o[ROWS * EMB];     // attn-out fp16

#define SCALE_L2E 0.180336880f         // 0.125 * log2(e)

// ============================================================================
// asm helpers (plain sm_80+ PTX — legal on target sm_103)
// ============================================================================
__device__ __forceinline__ uint32_t smem_to_u32(const void* p) {
    uint32_t a;
    asm("{ .reg .u64 t; cvta.to.shared.u64 t, %1; cvt.u32.u64 %0, t; }"
        : "=r"(a) : "l"(p));
    return a;
}

#define CP_ASYNC16(dst, src) \
    asm volatile("cp.async.cg.shared.global [%0], [%1], 16;" \
                 :: "r"(dst), "l"(__cvta_generic_to_global(src)) : "memory")
#define CP_COMMIT() asm volatile("cp.async.commit_group;" ::: "memory")
#define CP_WAIT1()  asm volatile("cp.async.wait_group 1;" ::: "memory")

#define LDSM_X4(r0, r1, r2, r3, addr) \
    asm volatile("ldmatrix.sync.aligned.m8n8.x4.shared.b16 {%0,%1,%2,%3}, [%4];" \
                 : "=r"(r0), "=r"(r1), "=r"(r2), "=r"(r3) : "r"(addr))
#define LDSM_X4T(r0, r1, r2, r3, addr) \
    asm volatile("ldmatrix.sync.aligned.m8n8.x4.trans.shared.b16 {%0,%1,%2,%3}, [%4];" \
                 : "=r"(r0), "=r"(r1), "=r"(r2), "=r"(r3) : "r"(addr))

#define MMA_F16(d, a, b0v, b1v) \
    asm volatile("mma.sync.aligned.m16n8k16.row.col.f32.f16.f16.f32 " \
                 "{%0,%1,%2,%3}, {%4,%5,%6,%7}, {%8,%9}, {%0,%1,%2,%3};" \
                 : "+f"((d)[0]), "+f"((d)[1]), "+f"((d)[2]), "+f"((d)[3]) \
                 : "r"((a)[0]), "r"((a)[1]), "r"((a)[2]), "r"((a)[3]), \
                   "r"(b0v), "r"(b1v))

// pack two f32 -> f16x2 (first arg in low half)
__device__ __forceinline__ uint32_t pack_f16x2(float lo, float hi) {
    uint32_t r;
    asm("cvt.rn.f16x2.f32 %0, %1, %2;" : "=r"(r) : "f"(hi), "f"(lo));
    return r;
}
#define H2EXP2(d, s) asm("ex2.approx.f16x2 %0, %1;" : "=r"(d) : "r"(s))
#define EX2F(d, s)   asm("ex2.approx.f32 %0, %1;"   : "=f"(d) : "f"(s))

// ============================================================================
// Unified prep (one launch): W_qkv^T, W_out^T (fp16), x (fp16).
// ============================================================================
__global__ void prep_all(const float* __restrict__ x,
                         const float* __restrict__ W_qkv,
                         const float* __restrict__ W_out)
{
    const int bid = blockIdx.x;
    const int tid = threadIdx.x;
    if (bid < 4096) {
        __shared__ float t[32][33];
        const float* W; __half* Wt; int K, N, n0, k0;
        if (bid < 3072) {
            W = W_qkv; Wt = g_wt1; K = EMB; N = D3;
            n0 = (bid % 96) * 32; k0 = (bid / 96) * 32;
        } else {
            const int b2 = bid - 3072;
            W = W_out; Wt = g_wt2; K = EMB; N = EMB;
            n0 = (b2 % 32) * 32; k0 = (b2 / 32) * 32;
        }
        const int tx = tid & 31, ty = tid >> 5;   // 32 x 8
#pragma unroll
        for (int j = 0; j < 32; j += 8)
            t[ty + j][tx] = W[(long)(k0 + ty + j) * N + n0 + tx];
        __syncthreads();
#pragma unroll
        for (int j = 0; j < 32; j += 8) {
            const int n = n0 + ty + j, k = k0 + tx;
            Wt[(long)n * K + k] = __float2half_rn(t[tx][ty + j]);
        }
    } else {
        const long i = (long)(bid - 4096) * 256 + tid;
        float4 v = ((const float4*)x)[i];
        uint2 u;
        u.x = pack_f16x2(v.x, v.y);
        u.y = pack_f16x2(v.z, v.w);
        ((uint2*)g_x)[i] = u;
    }
}

// ============================================================================
// HMMA GEMM + bias (at mma.sync rt=16 ceiling — unchanged).
// MODE 0 additionally pre-scales the Q region (cols < EMB) by SCALE_L2E.
// ============================================================================
#define STG 20480
#define GEMM_SMEM (4 * STG)

template <int MODE>
__global__ __launch_bounds__(256, 2)
void gemm_tc(const float* __restrict__ bias, float* __restrict__ Cout)
{
    const __half* A  = (MODE == 0) ? g_x : g_o;
    const __half* Bw = (MODE == 0) ? g_wt1 : g_wt2;
    const int N = (MODE == 0) ? D3 : EMB;
    const int K = EMB;

    extern __shared__ char smem[];
    const uint32_t sb = smem_to_u32(smem);
    const int tid = threadIdx.x;
    const int wid = tid >> 5, lane = tid & 31;
    const int wm = wid & 3, wn = wid >> 2;
    const int m0 = blockIdx.y * 128, n0 = blockIdx.x * 128;

    const __half* csrc[4];
    uint32_t cdst[4];
#pragma unroll
    for (int i = 0; i < 4; i++) {
        int g = i * 256 + tid;
        int sub = g >> 9, c = g & 511, row = c >> 2, ch = c & 3;
        const __half* bp = (sub == 0) ? A + (long)m0 * K : Bw + (long)n0 * K;
        csrc[i] = bp + (long)row * K + ch * 8;
        cdst[i] = sb + sub * 10240 + row * 80 + ch * 16;
    }

    auto issue_stage = [&](int s) {
        if (s >= NCK) return;                 // tail: empty group (commit-only)
        const uint32_t bo = (uint32_t)(s & 3) * STG;
#pragma unroll
        for (int i = 0; i < 4; i++) {
            CP_ASYNC16(cdst[i] + bo, csrc[i]);
            csrc[i] += 32;
        }
    };

    issue_stage(0); issue_stage(1); CP_COMMIT();
    issue_stage(2); issue_stage(3); CP_COMMIT();

    const uint32_t a_base = sb + (wm * 32 + (lane & 15)) * 80 + (lane >> 4) * 16;
    const uint32_t b_base = sb + 10240 +
        (wn * 64 + (lane & 7) + ((lane >> 4) & 1) * 8) * 80 + ((lane >> 3) & 1) * 16;

    float acc[2][8][4];
#pragma unroll
    for (int mf = 0; mf < 2; mf++)
#pragma unroll
        for (int nf = 0; nf < 8; nf++)
#pragma unroll
            for (int q = 0; q < 4; q++) acc[mf][nf][q] = 0.f;

    auto compute_stage = [&](int ck) {
        const uint32_t bofs = (uint32_t)(ck & 3) * STG;
#pragma unroll
        for (int kk = 0; kk < 2; kk++) {
            const uint32_t ko = bofs + kk * 32;
            uint32_t a4[2][4], b44[4][4];
            LDSM_X4(a4[0][0], a4[0][1], a4[0][2], a4[0][3], a_base + ko);
            LDSM_X4(a4[1][0], a4[1][1], a4[1][2], a4[1][3], a_base + 1280 + ko);
#pragma unroll
            for (int nf = 0; nf < 4; nf++)
                LDSM_X4(b44[nf][0], b44[nf][1], b44[nf][2], b44[nf][3],
                        b_base + nf * 1280 + ko);
#pragma unroll
            for (int nf = 0; nf < 4; nf++) {
                MMA_F16(acc[0][nf * 2 + 0], a4[0], b44[nf][0], b44[nf][1]);
                MMA_F16(acc[1][nf * 2 + 0], a4[1], b44[nf][0], b44[nf][1]);
                MMA_F16(acc[0][nf * 2 + 1], a4[0], b44[nf][2], b44[nf][3]);
                MMA_F16(acc[1][nf * 2 + 1], a4[1], b44[nf][2], b44[nf][3]);
            }
        }
    };

    for (int j = 0; j < NCK / 2; j++) {
        CP_WAIT1();
        __syncthreads();
        compute_stage(2 * j);
        compute_stage(2 * j + 1);
        __syncthreads();
        issue_stage(2 * j + 4);
        issue_stage(2 * j + 5);
        CP_COMMIT();
    }

    const int gid = lane >> 2, tig = lane & 3;
#pragma unroll
    for (int mf = 0; mf < 2; mf++) {
#pragma unroll
        for (int nf = 0; nf < 8; nf++) {
            const int col = n0 + wn * 64 + nf * 8 + tig * 2;
            const float bx0 = bias[col], bx1 = bias[col + 1];
            const int r0 = m0 + wm * 32 + mf * 16 + gid;
            float v00 = acc[mf][nf][0] + bx0, v01 = acc[mf][nf][1] + bx1;
            float v10 = acc[mf][nf][2] + bx0, v11 = acc[mf][nf][3] + bx1;
            if (MODE == 1) {
                float2 a0 = {v00, v01}, a1 = {v10, v11};
                *(float2*)&Cout[(long)r0 * N + col] = a0;
                *(float2*)&Cout[(long)(r0 + 8) * N + col] = a1;
            } else {
                if (n0 < EMB) {   // Q region: fold softmax scale into Q
                    v00 *= SCALE_L2E; v01 *= SCALE_L2E;
                    v10 *= SCALE_L2E; v11 *= SCALE_L2E;
                }
                *(uint32_t*)&g_qkv[(long)r0 * N + col] = pack_f16x2(v00, v01);
                *(uint32_t*)&g_qkv[(long)(r0 + 8) * N + col] = pack_f16x2(v10, v11);
            }
        }
    }
}

// ============================================================================
// HMMA flash attention v4, causal. 4 warps x 32 q-rows, Q in registers,
// ones-MMA row sums (now fused into deferred PV), ex2.approx.f16x2 exp.
// Deferred PV overlaps softmax; V ring 5 / K ring 4.
// Fully-masked warps skip QK+softmax+PV on the final diagonal stage.
// Warp-voted skip of oacc/lacc rescale when the running max is unchanged.
// ============================================================================
#define APITCH 144
#define SQ_BYTES  (128 * APITCH)          // 18432 (Q staging)
#define SKV_BYTES (64 * APITCH)           // 9216  (one K or V buffer)
#define ATTN_SMEM (SQ_BYTES + 4 * SKV_BYTES + 5 * SKV_BYTES)   // 101376

__global__ __launch_bounds__(128, 2)
void attn_tc()
{
    extern __shared__ char smem[];
    const uint32_t sb = smem_to_u32(smem);
    const uint32_t sQ = sb;
    const uint32_t sK0 = sb + SQ_BYTES;              // K ring: + (s&3)*9216
    const uint32_t sV0 = sK0 + 4 * SKV_BYTES;        // V ring: + (s%5)*9216

    const int qt = gridDim.x - 1 - blockIdx.x;   // long blocks first
    const int h  = blockIdx.y;
    const int b  = blockIdx.z;
    const int tid = threadIdx.x;
    const int wid = tid >> 5, lane = tid & 31;
    const int gid = lane >> 2, tig = lane & 3;
    const int q0 = qt * 128;
    const long rowbase = (long)b * SEQ;
    const int nk = 2 * qt + 2;                   // even
    const uint32_t ONES = 0x3C003C00u;           // half2(1,1)

    auto issue_k = [&](int s) {
        if (s >= nk) return;                     // tail: empty group
        const uint32_t kb = sK0 + (uint32_t)(s & 3) * SKV_BYTES;
#pragma unroll
        for (int it = 0; it < 4; it++) {
            int g = it * 128 + tid;
            int row = g >> 3, ch = g & 7;
            CP_ASYNC16(kb + row * APITCH + ch * 16,
                       g_qkv + (rowbase + s * 64 + row) * D3 + EMB + h * HSZ + ch * 8);
        }
    };
    auto issue_v = [&](int s) {
        if (s >= nk) return;
        const uint32_t vb = sV0 + (uint32_t)(s % 5) * SKV_BYTES;
#pragma unroll
        for (int it = 0; it < 4; it++) {
            int g = it * 128 + tid;
            int row = g >> 3, ch = g & 7;
            CP_ASYNC16(vb + row * APITCH + ch * 16,
                       g_qkv + (rowbase + s * 64 + row) * D3 + 2 * EMB + h * HSZ + ch * 8);
        }
    };

    // prologue: group0 = Q + K/V(0,1); group1 = K/V(2,3)
#pragma unroll
    for (int it = 0; it < 8; it++) {
        int g = it * 128 + tid;
        int row = g >> 3, ch = g & 7;
        CP_ASYNC16(sQ + row * APITCH + ch * 16,
                   g_qkv + (rowbase + q0 + row) * D3 + h * HSZ + ch * 8);
    }
    issue_k(0); issue_k(1); issue_v(0); issue_v(1); CP_COMMIT();
    issue_k(2); issue_k(3); issue_v(2); issue_v(3); CP_COMMIT();

    const uint32_t bk_off = ((lane & 7) + ((lane >> 4) & 1) * 8) * APITCH
                              + ((lane >> 3) & 1) * 16;
    const uint32_t v_off = ((lane & 7) + ((lane >> 3) & 1) * 8) * APITCH
                              + (lane >> 4) * 16;

    uint32_t qreg[2][4][4];                      // [mf][ks][reg], loaded once
    float oacc[2][8][4];
    float lacc[2][4];
    float mrow[2][2];
    float sacc[2][8][4];
    uint32_t pa[2][4][4];                        // P frags (persist one stage)
#pragma unroll
    for (int mf = 0; mf < 2; mf++) {
        mrow[mf][0] = -1e30f; mrow[mf][1] = -1e30f;
#pragma unroll
        for (int q = 0; q < 4; q++) lacc[mf][q] = 0.f;
#pragma unroll
        for (int df = 0; df < 8; df++)
#pragma unroll
            for (int q = 0; q < 4; q++) oacc[mf][df][q] = 0.f;
    }

    const int qrA0 = q0 + wid * 32 + gid;        // mf0 rows: qrA0, qrA0+8

    // ---- QK^T for stage kt: sacc = Qreg x K[slot kt&3] ----
    auto do_qk = [&](int kt) {
        const uint32_t bk_base = sK0 + (uint32_t)(kt & 3) * SKV_BYTES + bk_off;
#pragma unroll
        for (int mf = 0; mf < 2; mf++)
#pragma unroll
            for (int nf = 0; nf < 8; nf++)
#pragma unroll
                for (int q = 0; q < 4; q++) sacc[mf][nf][q] = 0.f;
#pragma unroll
        for (int ks = 0; ks < 4; ks++) {
            uint32_t k44[4][4];
#pragma unroll
            for (int nb = 0; nb < 4; nb++)
                LDSM_X4(k44[nb][0], k44[nb][1], k44[nb][2], k44[nb][3],
                        bk_base + nb * (16 * APITCH) + ks * 32);
#pragma unroll
            for (int nb = 0; nb < 4; nb++) {
                MMA_F16(sacc[0][nb * 2 + 0], qreg[0][ks], k44[nb][0], k44[nb][1]);
                MMA_F16(sacc[1][nb * 2 + 0], qreg[1][ks], k44[nb][0], k44[nb][1]);
                MMA_F16(sacc[0][nb * 2 + 1], qreg[0][ks], k44[nb][2], k44[nb][3]);
                MMA_F16(sacc[1][nb * 2 + 1], qreg[1][ks], k44[nb][2], k44[nb][3]);
            }
        }
    };

    // ---- PV for stage kt: oacc += pa x V[slot kt%5];  lacc += pa x ones ----
    auto do_pv = [&](int kt) {
        const uint32_t v_base = sV0 + (uint32_t)(kt % 5) * SKV_BYTES + v_off;
#pragma unroll
        for (int ks = 0; ks < 4; ks++) {
            uint32_t v44[4][4];
#pragma unroll
            for (int nb = 0; nb < 4; nb++)
                LDSM_X4T(v44[nb][0], v44[nb][1], v44[nb][2], v44[nb][3],
                         v_base + ks * (16 * APITCH) + nb * 32);
            MMA_F16(lacc[0], pa[0][ks], ONES, ONES);
            MMA_F16(lacc[1], pa[1][ks], ONES, ONES);
#pragma unroll
            for (int nb = 0; nb < 4; nb++) {
                MMA_F16(oacc[0][nb * 2 + 0], pa[0][ks], v44[nb][0], v44[nb][1]);
                MMA_F16(oacc[1][nb * 2 + 0], pa[1][ks], v44[nb][0], v44[nb][1]);
                MMA_F16(oacc[0][nb * 2 + 1], pa[0][ks], v44[nb][2], v44[nb][3]);
                MMA_F16(oacc[1][nb * 2 + 1], pa[1][ks], v44[nb][2], v44[nb][3]);
            }
        }
    };

    // ---- softmax for stage kt: mask, max, (voted) rescale, pa = exp2 ----
    auto do_sm = [&](int kt) {
        const int k0 = kt * 64;
        if (kt >= 2 * qt) {
#pragma unroll
            for (int mf = 0; mf < 2; mf++) {
                const int ra = qrA0 + mf * 16, rb = ra + 8;
#pragma unroll
                for (int nf = 0; nf < 8; nf++) {
                    const int c = k0 + nf * 8 + 2 * tig;
                    if (c     > ra) sacc[mf][nf][0] = -1e30f;
                    if (c + 1 > ra) sacc[mf][nf][1] = -1e30f;
                    if (c     > rb) sacc[mf][nf][2] = -1e30f;
                    if (c + 1 > rb) sacc[mf][nf][3] = -1e30f;
                }
            }
        }
#pragma unroll
        for (int mf = 0; mf < 2; mf++) {
            float tm0 = -1e30f, tm1 = -1e30f;
#pragma unroll
            for (int nf = 0; nf < 8; nf++) {
                tm0 = fmaxf(tm0, fmaxf(sacc[mf][nf][0], sacc[mf][nf][1]));
                tm1 = fmaxf(tm1, fmaxf(sacc[mf][nf][2], sacc[mf][nf][3]));
            }
            tm0 = fmaxf(tm0, __shfl_xor_sync(0xffffffffu, tm0, 1));
            tm0 = fmaxf(tm0, __shfl_xor_sync(0xffffffffu, tm0, 2));
            tm1 = fmaxf(tm1, __shfl_xor_sync(0xffffffffu, tm1, 1));
            tm1 = fmaxf(tm1, __shfl_xor_sync(0xffffffffu, tm1, 2));

            const float mn0 = fmaxf(mrow[mf][0], tm0);
            const float mn1 = fmaxf(mrow[mf][1], tm1);
            float esc0, esc1;
            EX2F(esc0, mrow[mf][0] - mn0);
            EX2F(esc1, mrow[mf][1] - mn1);
            mrow[mf][0] = mn0; mrow[mf][1] = mn1;
            // warp-voted rescale skip: exact no-op when max unchanged (esc==1)
            if (!__all_sync(0xffffffffu, (esc0 == 1.f) & (esc1 == 1.f))) {
#pragma unroll
                for (int df = 0; df < 8; df++) {
                    oacc[mf][df][0] *= esc0; oacc[mf][df][1] *= esc0;
                    oacc[mf][df][2] *= esc1; oacc[mf][df][3] *= esc1;
                }
                lacc[mf][0] *= esc0; lacc[mf][1] *= esc0;
                lacc[mf][2] *= esc1; lacc[mf][3] *= esc1;
            }

#pragma unroll
            for (int ks = 0; ks < 4; ks++) {
                const int f0 = 2 * ks, f1 = 2 * ks + 1;
                uint32_t d0 = pack_f16x2(sacc[mf][f0][0] - mn0, sacc[mf][f0][1] - mn0);
                uint32_t d1 = pack_f16x2(sacc[mf][f0][2] - mn1, sacc[mf][f0][3] - mn1);
                uint32_t d2 = pack_f16x2(sacc[mf][f1][0] - mn0, sacc[mf][f1][1] - mn0);
                uint32_t d3 = pack_f16x2(sacc[mf][f1][2] - mn1, sacc[mf][f1][3] - mn1);
                H2EXP2(pa[mf][ks][0], d0);
                H2EXP2(pa[mf][ks][1], d1);
                H2EXP2(pa[mf][ks][2], d2);
                H2EXP2(pa[mf][ks][3], d3);
            }
        }
    };

    bool dead_tail = false;    // this warp skipped the final stage entirely
    for (int j = 0; j < nk / 2; j++) {
        CP_WAIT1();            // K/V stages 2j,2j+1 (+Q on j=0) landed
        __syncthreads();
        if (j == 0) {
#pragma unroll
            for (int mf = 0; mf < 2; mf++) {
                const uint32_t qb = sQ + (wid * 32 + mf * 16 + (lane & 15)) * APITCH
                                    + (lane >> 4) * 16;
#pragma unroll
                for (int ks = 0; ks < 4; ks++)
                    LDSM_X4(qreg[mf][ks][0], qreg[mf][ks][1],
                            qreg[mf][ks][2], qreg[mf][ks][3], qb + ks * 32);
            }
        }
        const int a = 2 * j, bs = 2 * j + 1;
        // fully-masked warps skip the entire final diagonal stage
        const bool deadb = (j == qt) && (wid < 2);

        do_qk(a);
        if (j > 0) do_pv(a - 1);     // deferred PV (+l-MMA) overlaps softmax(a)
        do_sm(a);

        if (!deadb) {
            do_qk(bs);
            do_pv(a);                // overlaps softmax(bs)
            do_sm(bs);
        } else {
            do_pv(a);                // still flush stage a's P
            dead_tail = true;
        }

        __syncthreads();
        issue_k(2 * j + 4); issue_k(2 * j + 5);
        issue_v(2 * j + 4); issue_v(2 * j + 5);
        CP_COMMIT();
    }
    if (!dead_tail) do_pv(nk - 1);   // final deferred PV (skipped: P would be 0)

    // ---- finalize: O = oacc / l (l from ones-MMA accumulator), fp16 ----
#pragma unroll
    for (int mf = 0; mf < 2; mf++) {
        const float inv0 = 1.f / lacc[mf][0];
        const float inv1 = 1.f / lacc[mf][2];
        const int ra = qrA0 + mf * 16, rb = ra + 8;
#pragma unroll
        for (int df = 0; df < 8; df++) {
            const int col = h * HSZ + df * 8 + 2 * tig;
            *(uint32_t*)&g_o[(rowbase + ra) * EMB + col] =
                pack_f16x2(oacc[mf][df][0] * inv0, oacc[mf][df][1] * inv0);
            *(uint32_t*)&g_o[(rowbase + rb) * EMB + col] =
                pack_f16x2(oacc[mf][df][2] * inv1, oacc[mf][df][3] * inv1);
        }
    }
}

// ---------------------------------------------------------------------------
extern "C" void kernel_launch(void* const* d_in, const int* in_sizes, int n_in,
                              void* d_out, int out_size)
{
    const float* x     = (const float*)d_in[0];
    const float* W_qkv = (const float*)d_in[1];
    const float* b_qkv = (const float*)d_in[2];
    const float* W_out = (const float*)d_in[3];
    const float* b_out = (const float*)d_in[4];
    float* out = (float*)d_out;

    // 0) unified prep: W transposes (fp16) + x convert — one launch
    prep_all<<<8192, 256>>>(x, W_qkv, W_out);

    // 1) QKV projection (HMMA fp16; Q region pre-scaled by 0.125*log2e)
    cudaFuncSetAttribute(gemm_tc<0>, cudaFuncAttributeMaxDynamicSharedMemorySize, GEMM_SMEM);
    gemm_tc<0><<<dim3(D3 / 128, ROWS / 128), 256, GEMM_SMEM>>>(b_qkv, nullptr);

    // 2) causal flash attention v4 (dead-stage skip + voted rescale skip)
    cudaFuncSetAttribute(attn_tc, cudaFuncAttributeMaxDynamicSharedMemorySize, ATTN_SMEM);
    attn_tc<<<dim3(SEQ / 128, NH, BATCH), 128, ATTN_SMEM>>>();

    // 3) output projection (HMMA fp16), fp32 out + bias
    cudaFuncSetAttribute(gemm_tc<1>, cudaFuncAttributeMaxDynamicSharedMemorySize, GEMM_SMEM);
    gemm_tc<1><<<dim3(EMB / 128, ROWS / 128), 256, GEMM_SMEM>>>(b_out, out);
}